// round 16
// baseline (speedup 1.0000x reference)
#include <cuda_runtime.h>
#include <cuda_bf16.h>
#include <cstdint>

#define BATCH 8
#define HW    4096
#define CIN   256
#define DQK   128
#define DV    256
#define QS2C  0.12751741f   // (1/sqrt(128)) * log2(e)

__device__ __nv_bfloat16 g_Q[(size_t)BATCH * HW * DQK];    // [b][n][d]
__device__ __nv_bfloat16 g_K[(size_t)BATCH * HW * DQK];    // [b][n][d]
__device__ __nv_bfloat16 g_V[(size_t)BATCH * DV * HW];     // [b][e][n] e-major
__device__ __nv_bfloat16 g_Hb[(size_t)BATCH * HW * DV];    // [b][n][e], normalized
__device__ float         g_Qn[(size_t)BATCH * HW];         // QS2C*1.01*||q||
__device__ float         g_Kn[(size_t)BATCH * HW];         // ||k||

__device__ __forceinline__ uint32_t smem_u32(const void* p) {
    return (uint32_t)__cvta_generic_to_shared(p);
}
__device__ __forceinline__ void ldm_x4(uint32_t& r0, uint32_t& r1, uint32_t& r2, uint32_t& r3, uint32_t addr) {
    asm volatile("ldmatrix.sync.aligned.m8n8.x4.shared.b16 {%0,%1,%2,%3},[%4];"
                 : "=r"(r0), "=r"(r1), "=r"(r2), "=r"(r3) : "r"(addr));
}
__device__ __forceinline__ void ldm_x4t(uint32_t& r0, uint32_t& r1, uint32_t& r2, uint32_t& r3, uint32_t addr) {
    asm volatile("ldmatrix.sync.aligned.m8n8.x4.trans.shared.b16 {%0,%1,%2,%3},[%4];"
                 : "=r"(r0), "=r"(r1), "=r"(r2), "=r"(r3) : "r"(addr));
}
__device__ __forceinline__ void mma_bf16(float& c0, float& c1, float& c2, float& c3,
                                         uint32_t a0, uint32_t a1, uint32_t a2, uint32_t a3,
                                         uint32_t b0, uint32_t b1) {
    asm volatile("mma.sync.aligned.m16n8k16.row.col.f32.bf16.bf16.f32 "
                 "{%0,%1,%2,%3},{%4,%5,%6,%7},{%8,%9},{%0,%1,%2,%3};"
                 : "+f"(c0), "+f"(c1), "+f"(c2), "+f"(c3)
                 : "r"(a0), "r"(a1), "r"(a2), "r"(a3), "r"(b0), "r"(b1));
}
__device__ __forceinline__ uint32_t packbf2(float lo, float hi) {
    __nv_bfloat162 v = __floats2bfloat162_rn(lo, hi);
    return *reinterpret_cast<uint32_t*>(&v);
}
__device__ __forceinline__ float ex2f(float x) {
    float y; asm("ex2.approx.f32 %0,%1;" : "=f"(y) : "f"(x)); return y;
}
#define CP16(saddr, gptr) \
    asm volatile("cp.async.cg.shared.global [%0],[%1],16;" :: "r"(saddr), "l"(gptr))
#define CP_COMMIT() asm volatile("cp.async.commit_group;")
#define CP_WAIT1()  asm volatile("cp.async.wait_group 1;")
#define CP_WAIT0()  asm volatile("cp.async.wait_group 0;")

// ---------------- projection GEMM (bf16 mma), fused weight-cvt + input-cvt + norms ----
#define PSTR 72
#define PROJ_SMEM ((128 * PSTR + 512 * PSTR) * 2)

__global__ __launch_bounds__(256, 1) void proj_mma_kernel(
        const float* __restrict__ x, const float* __restrict__ y,
        const float* __restrict__ Wq, const float* __restrict__ Wk, const float* __restrict__ Wv,
        const float* __restrict__ bq, const float* __restrict__ bk, const float* __restrict__ bv) {
    extern __shared__ __nv_bfloat16 psmem[];
    __nv_bfloat16* sX = psmem;
    __nv_bfloat16* sY = psmem + 64 * PSTR;
    __nv_bfloat16* sW = psmem + 128 * PSTR;
    __shared__ float sBias[512];

    const int b = blockIdx.y, n0 = blockIdx.x * 64;
    const int tid = threadIdx.x, warp = tid >> 5, lane = tid & 31;
    const int mg = warp & 3, dg = warp >> 2;

    for (int i = tid; i < 512; i += 256)
        sBias[i] = (i < 128) ? bq[i] : (i < 256) ? bk[i - 128] : bv[i - 256];

    const float* Xf = x + (size_t)b * CIN * HW + n0;
    const float* Yf = y + (size_t)b * CIN * HW + n0;

    float acc[32][4];
    #pragma unroll
    for (int t = 0; t < 32; t++) { acc[t][0] = acc[t][1] = acc[t][2] = acc[t][3] = 0.f; }

    const int arow = (lane & 7) + ((lane >> 4) & 1) * 8;
    const int acol = mg * 16 + ((lane >> 3) & 1) * 8;
    const uint32_t aXbase = smem_u32(sX + arow * PSTR + acol);
    const uint32_t aYbase = smem_u32(sY + arow * PSTR + acol);
    const int brow = (lane & 7) + ((lane >> 4) & 1) * 8;
    const int bcol = ((lane >> 3) & 1) * 8;
    const uint32_t bWbase = smem_u32(sW + (dg * 256 + brow) * PSTR + bcol);

    // per-thread fixed weight row pointer for staging (r = u>>3 is tid-dependent, constant over ck)
    for (int ck = 0; ck < 4; ck++) {
        __syncthreads();
        #pragma unroll
        for (int j = 0; j < 4; j++) {
            int u = tid + j * 256;
            int r = u >> 3, c8 = (u & 7) * 8;
            const float* xs = Xf + (size_t)(ck * 64 + r) * HW + c8;
            const float* ys = Yf + (size_t)(ck * 64 + r) * HW + c8;
            float4 xa = *reinterpret_cast<const float4*>(xs);
            float4 xb2 = *reinterpret_cast<const float4*>(xs + 4);
            float4 ya = *reinterpret_cast<const float4*>(ys);
            float4 yb2 = *reinterpret_cast<const float4*>(ys + 4);
            *reinterpret_cast<uint4*>(sX + r * PSTR + c8) =
                make_uint4(packbf2(xa.x, xa.y), packbf2(xa.z, xa.w),
                           packbf2(xb2.x, xb2.y), packbf2(xb2.z, xb2.w));
            *reinterpret_cast<uint4*>(sY + r * PSTR + c8) =
                make_uint4(packbf2(ya.x, ya.y), packbf2(ya.z, ya.w),
                           packbf2(yb2.x, yb2.y), packbf2(yb2.z, yb2.w));
        }
        #pragma unroll
        for (int j = 0; j < 16; j++) {
            int u = tid + j * 256;
            int r = u >> 3, c8 = (u & 7) * 8;
            const float* wsrc = ((r < 128) ? (Wq + (size_t)r * 256)
                               : (r < 256) ? (Wk + (size_t)(r - 128) * 256)
                                           : (Wv + (size_t)(r - 256) * 256)) + ck * 64 + c8;
            float4 wa = *reinterpret_cast<const float4*>(wsrc);
            float4 wb = *reinterpret_cast<const float4*>(wsrc + 4);
            *reinterpret_cast<uint4*>(sW + r * PSTR + c8) =
                make_uint4(packbf2(wa.x, wa.y), packbf2(wa.z, wa.w),
                           packbf2(wb.x, wb.y), packbf2(wb.z, wb.w));
        }
        __syncthreads();

        #pragma unroll
        for (int kk = 0; kk < 4; kk++) {
            uint32_t ax0, ax1, ax2, ax3;
            ldm_x4t(ax0, ax1, ax2, ax3, aXbase + kk * 16 * PSTR * 2);
            uint32_t ay0 = ax0, ay1 = ax1, ay2 = ax2, ay3 = ax3;
            if (dg == 0) ldm_x4t(ay0, ay1, ay2, ay3, aYbase + kk * 16 * PSTR * 2);
            #pragma unroll
            for (int t2 = 0; t2 < 16; t2++) {
                uint32_t b0, b1, b2, b3;
                ldm_x4(b0, b1, b2, b3, bWbase + (t2 * 16 * PSTR + kk * 16) * 2);
                if (dg == 0 && t2 < 8) {
                    mma_bf16(acc[2*t2][0],   acc[2*t2][1],   acc[2*t2][2],   acc[2*t2][3],   ay0, ay1, ay2, ay3, b0, b1);
                    mma_bf16(acc[2*t2+1][0], acc[2*t2+1][1], acc[2*t2+1][2], acc[2*t2+1][3], ay0, ay1, ay2, ay3, b2, b3);
                } else {
                    mma_bf16(acc[2*t2][0],   acc[2*t2][1],   acc[2*t2][2],   acc[2*t2][3],   ax0, ax1, ax2, ax3, b0, b1);
                    mma_bf16(acc[2*t2+1][0], acc[2*t2+1][1], acc[2*t2+1][2], acc[2*t2+1][3], ax0, ax1, ax2, ax3, b2, b3);
                }
            }
        }
    }

    const int r = n0 + mg * 16 + (lane >> 2);
    const int cpair = (lane & 3) * 2;
    float qn0 = 0.f, qn1 = 0.f, kn0 = 0.f, kn1 = 0.f;
    #pragma unroll
    for (int t = 0; t < 32; t++) {
        int d0 = dg * 256 + t * 8 + cpair;
        float bv0 = sBias[d0], bv1 = sBias[d0 + 1];
        float v00 = acc[t][0] + bv0, v01 = acc[t][1] + bv1;
        float v10 = acc[t][2] + bv0, v11 = acc[t][3] + bv1;
        if (d0 < 256) {
            __nv_bfloat16* dst = (d0 < 128) ? g_Q : g_K;
            int ld = d0 & 127;
            *reinterpret_cast<uint32_t*>(dst + ((size_t)b * HW + r) * DQK + ld) = packbf2(v00, v01);
            *reinterpret_cast<uint32_t*>(dst + ((size_t)b * HW + r + 8) * DQK + ld) = packbf2(v10, v11);
            if (d0 < 128) { qn0 += v00 * v00 + v01 * v01; qn1 += v10 * v10 + v11 * v11; }
            else          { kn0 += v00 * v00 + v01 * v01; kn1 += v10 * v10 + v11 * v11; }
        } else {
            int e = d0 - 256;
            __nv_bfloat16* base = g_V + (size_t)b * DV * HW;
            base[(size_t)e * HW + r]           = __float2bfloat16(v00);
            base[(size_t)(e + 1) * HW + r]     = __float2bfloat16(v01);
            base[(size_t)e * HW + r + 8]       = __float2bfloat16(v10);
            base[(size_t)(e + 1) * HW + r + 8] = __float2bfloat16(v11);
        }
    }
    if (dg == 0) {
        qn0 += __shfl_xor_sync(0xffffffffu, qn0, 1); qn0 += __shfl_xor_sync(0xffffffffu, qn0, 2);
        qn1 += __shfl_xor_sync(0xffffffffu, qn1, 1); qn1 += __shfl_xor_sync(0xffffffffu, qn1, 2);
        kn0 += __shfl_xor_sync(0xffffffffu, kn0, 1); kn0 += __shfl_xor_sync(0xffffffffu, kn0, 2);
        kn1 += __shfl_xor_sync(0xffffffffu, kn1, 1); kn1 += __shfl_xor_sync(0xffffffffu, kn1, 2);
        if ((lane & 3) == 0) {
            const float qsc = QS2C * 1.01f;
            g_Qn[(size_t)b * HW + r]     = sqrtf(qn0) * qsc;
            g_Qn[(size_t)b * HW + r + 8] = sqrtf(qn1) * qsc;
            g_Kn[(size_t)b * HW + r]     = sqrtf(kn0);
            g_Kn[(size_t)b * HW + r + 8] = sqrtf(kn1);
        }
    }
}

// ---------------- flash: bf16, bound softmax, Q in regs, triple-buffered KV,
//                  software-pipelined ldmatrix (R14 best) ----------------
#define QSTRB 272
#define VSTRB 144
#define KBUF (64 * QSTRB)
#define VBUF (256 * VSTRB)
#define SK_OFF (128 * QSTRB)
#define SV_OFF (SK_OFF + 3 * KBUF)
#define FLASH_SMEM (SV_OFF + 3 * VBUF)   // 197632

__global__ __launch_bounds__(256, 1) void flash_kernel() {
    extern __shared__ uint8_t fsm[];
    uint8_t* sQ = fsm;
    uint8_t* sK = fsm + SK_OFF;
    uint8_t* sV = fsm + SV_OFF;
    __shared__ float s_km[8];

    const int b = blockIdx.y, q0 = blockIdx.x * 128;
    const int tid = threadIdx.x, warp = tid >> 5, lane = tid & 31;
    const uint8_t* Qg = reinterpret_cast<const uint8_t*>(g_Q + ((size_t)b * HW + q0) * DQK);
    const uint8_t* Kg = reinterpret_cast<const uint8_t*>(g_K + (size_t)b * HW * DQK);
    const uint8_t* Vg = reinterpret_cast<const uint8_t*>(g_V + (size_t)b * DV * HW);

    #pragma unroll
    for (int j = 0; j < 8; j++) {
        int u = tid + j * 256; int r = u >> 4, s = (u & 15) * 16;
        CP16(smem_u32(sQ + r * QSTRB + s), Qg + (size_t)r * 256 + s);
    }
    #pragma unroll
    for (int j = 0; j < 4; j++) {
        int u = tid + j * 256; int r = u >> 4, s = (u & 15) * 16;
        CP16(smem_u32(sK + r * QSTRB + s), Kg + (size_t)r * 256 + s);
    }
    #pragma unroll
    for (int j = 0; j < 8; j++) {
        int u = tid + j * 256; int e = u >> 3, s = (u & 7) * 16;
        CP16(smem_u32(sV + e * VSTRB + s), Vg + (size_t)e * (HW * 2) + s);
    }
    CP_COMMIT();
    #pragma unroll
    for (int j = 0; j < 4; j++) {
        int u = tid + j * 256; int r = u >> 4, s = (u & 15) * 16;
        CP16(smem_u32(sK + KBUF + r * QSTRB + s), Kg + (size_t)(64 + r) * 256 + s);
    }
    #pragma unroll
    for (int j = 0; j < 8; j++) {
        int u = tid + j * 256; int e = u >> 3, s = (u & 7) * 16;
        CP16(smem_u32(sV + VBUF + e * VSTRB + s), Vg + (size_t)e * (HW * 2) + 128 + s);
    }
    CP_COMMIT();

    {
        float km = 0.f;
        const float* Kn = g_Kn + (size_t)b * HW;
        #pragma unroll
        for (int i = 0; i < HW / 256; i++) km = fmaxf(km, Kn[tid + i * 256]);
        #pragma unroll
        for (int o = 16; o > 0; o >>= 1) km = fmaxf(km, __shfl_xor_sync(0xffffffffu, km, o));
        if (lane == 0) s_km[warp] = km;
    }

    float O[32][4];
    #pragma unroll
    for (int n = 0; n < 32; n++) { O[n][0] = O[n][1] = O[n][2] = O[n][3] = 0.f; }
    float l0 = 0.f, l1 = 0.f;
    float m0 = 0.f, m1 = 0.f;

    const int prow = lane >> 2;
    const uint32_t aQ = smem_u32(sQ + (warp * 16 + (lane & 15)) * QSTRB + ((lane >> 4) & 1) * 16);
    const int bRow = (lane & 7) + ((lane >> 4) & 1) * 8;
    const int bCol = ((lane >> 3) & 1) * 16;
    uint32_t qf[8][4];
    uint32_t rb[3][4];

    for (int t = 0; t < 64; t++) {
        if (t < 63) { CP_WAIT1(); } else { CP_WAIT0(); }
        __syncthreads();

        if (t + 2 < 64) {
            int kv2 = (t + 2) * 64;
            uint8_t* dK = sK + ((t + 2) % 3) * KBUF;
            uint8_t* dV = sV + ((t + 2) % 3) * VBUF;
            #pragma unroll
            for (int j = 0; j < 4; j++) {
                int u = tid + j * 256; int r = u >> 4, s = (u & 15) * 16;
                CP16(smem_u32(dK + r * QSTRB + s), Kg + (size_t)(kv2 + r) * 256 + s);
            }
            #pragma unroll
            for (int j = 0; j < 8; j++) {
                int u = tid + j * 256; int e = u >> 3, s = (u & 7) * 16;
                CP16(smem_u32(dV + e * VSTRB + s), Vg + (size_t)e * (HW * 2) + kv2 * 2 + s);
            }
            CP_COMMIT();
        }

        if (t == 0) {
            float kmax = s_km[0];
            #pragma unroll
            for (int w = 1; w < 8; w++) kmax = fmaxf(kmax, s_km[w]);
            m0 = g_Qn[(size_t)b * HW + q0 + warp * 16 + prow] * kmax;
            m1 = g_Qn[(size_t)b * HW + q0 + warp * 16 + prow + 8] * kmax;
            #pragma unroll
            for (int kk = 0; kk < 8; kk++)
                ldm_x4(qf[kk][0], qf[kk][1], qf[kk][2], qf[kk][3], aQ + kk * 32);
        }

        const int bi = t % 3;
        const uint32_t bK = smem_u32(sK + bi * KBUF + bRow * QSTRB + bCol);
        const uint32_t bV = smem_u32(sV + bi * VBUF + bRow * VSTRB + bCol);

        float S[8][4];
        #pragma unroll
        for (int j = 0; j < 8; j++) { S[j][0] = S[j][1] = S[j][2] = S[j][3] = 0.f; }
        ldm_x4(rb[0][0], rb[0][1], rb[0][2], rb[0][3], bK);
        ldm_x4(rb[1][0], rb[1][1], rb[1][2], rb[1][3], bK + 16 * QSTRB);
        #pragma unroll
        for (int s5 = 0; s5 < 32; s5++) {
            if (s5 + 2 < 32) {
                int s2 = s5 + 2, kk2 = s2 >> 2, j22 = s2 & 3;
                ldm_x4(rb[s2 % 3][0], rb[s2 % 3][1], rb[s2 % 3][2], rb[s2 % 3][3],
                       bK + j22 * 16 * QSTRB + kk2 * 32);
            }
            int kk = s5 >> 2, j2 = s5 & 3;
            uint32_t* bb = rb[s5 % 3];
            mma_bf16(S[2*j2][0],   S[2*j2][1],   S[2*j2][2],   S[2*j2][3],
                     qf[kk][0], qf[kk][1], qf[kk][2], qf[kk][3], bb[0], bb[1]);
            mma_bf16(S[2*j2+1][0], S[2*j2+1][1], S[2*j2+1][2], S[2*j2+1][3],
                     qf[kk][0], qf[kk][1], qf[kk][2], qf[kk][3], bb[2], bb[3]);
        }

        float rs0 = 0.f, rs1 = 0.f;
        #pragma unroll
        for (int j = 0; j < 8; j++) {
            S[j][0] = ex2f(fmaf(S[j][0], QS2C, -m0));
            S[j][1] = ex2f(fmaf(S[j][1], QS2C, -m0));
            S[j][2] = ex2f(fmaf(S[j][2], QS2C, -m1));
            S[j][3] = ex2f(fmaf(S[j][3], QS2C, -m1));
            rs0 += S[j][0] + S[j][1];
            rs1 += S[j][2] + S[j][3];
        }
        l0 += rs0;
        l1 += rs1;

        uint32_t a0 = 0, a1 = 0, a2 = 0, a3 = 0;
        ldm_x4(rb[0][0], rb[0][1], rb[0][2], rb[0][3], bV);
        ldm_x4(rb[1][0], rb[1][1], rb[1][2], rb[1][3], bV + 16 * VSTRB);
        #pragma unroll
        for (int s5 = 0; s5 < 64; s5++) {
            if (s5 + 2 < 64) {
                int s2 = s5 + 2, kc2 = s2 >> 4, ep2 = s2 & 15;
                ldm_x4(rb[s2 % 3][0], rb[s2 % 3][1], rb[s2 % 3][2], rb[s2 % 3][3],
                       bV + ep2 * 16 * VSTRB + kc2 * 32);
            }
            int kc = s5 >> 4, ep = s5 & 15;
            if (ep == 0) {
                a0 = packbf2(S[2*kc][0],   S[2*kc][1]);
                a1 = packbf2(S[2*kc][2],   S[2*kc][3]);
                a2 = packbf2(S[2*kc+1][0], S[2*kc+1][1]);
                a3 = packbf2(S[2*kc+1][2], S[2*kc+1][3]);
            }
            uint32_t* bb = rb[s5 % 3];
            mma_bf16(O[2*ep][0],   O[2*ep][1],   O[2*ep][2],   O[2*ep][3],   a0, a1, a2, a3, bb[0], bb[1]);
            mma_bf16(O[2*ep+1][0], O[2*ep+1][1], O[2*ep+1][2], O[2*ep+1][3], a0, a1, a2, a3, bb[2], bb[3]);
        }
    }

    l0 += __shfl_xor_sync(0xffffffffu, l0, 1);
    l0 += __shfl_xor_sync(0xffffffffu, l0, 2);
    l1 += __shfl_xor_sync(0xffffffffu, l1, 1);
    l1 += __shfl_xor_sync(0xffffffffu, l1, 2);
    const float inv0 = 1.f / l0, inv1 = 1.f / l1;
    const int r0 = q0 + warp * 16 + prow;
    uint32_t* H0 = reinterpret_cast<uint32_t*>(g_Hb + ((size_t)b * HW + r0) * DV) + (lane & 3);
    uint32_t* H1 = H0 + 8 * (DV / 2);
    #pragma unroll
    for (int n = 0; n < 32; n++) {
        H0[n * 4] = packbf2(O[n][0] * inv0, O[n][1] * inv0);
        H1[n * 4] = packbf2(O[n][2] * inv1, O[n][3] * inv1);
    }
}

// ---------------- output GEMM + residual (bf16 mma), fused weight-cvt ----------------
#define OSTR 72
#define OUT_SMEM ((256 * OSTR + 64 * OSTR) * 2)

__global__ __launch_bounds__(256) void out_mma_kernel(
        const float* __restrict__ x, const float* __restrict__ Wo,
        const float* __restrict__ bo, float* __restrict__ out) {
    extern __shared__ __nv_bfloat16 osmem[];
    __nv_bfloat16* sW = osmem;
    __nv_bfloat16* sH = osmem + 256 * OSTR;
    const int b = blockIdx.y, n0 = blockIdx.x * 64;
    const int tid = threadIdx.x, warp = tid >> 5, lane = tid & 31;

    const __nv_bfloat16* Hb = g_Hb + ((size_t)b * HW + n0) * DV;

    float acc[2][8][4];
    #pragma unroll
    for (int mt = 0; mt < 2; mt++)
        #pragma unroll
        for (int nt = 0; nt < 8; nt++) { acc[mt][nt][0] = acc[mt][nt][1] = acc[mt][nt][2] = acc[mt][nt][3] = 0.f; }

    const int arow = lane & 15;
    const int acol = ((lane >> 4) & 1) * 8;
    const uint32_t aBase = smem_u32(sW + (warp * 32 + arow) * OSTR + acol);
    const int brow = (lane & 7) + ((lane >> 4) & 1) * 8;
    const int bcol = ((lane >> 3) & 1) * 8;
    const uint32_t bBase = smem_u32(sH + brow * OSTR + bcol);

    for (int ck = 0; ck < 4; ck++) {
        __syncthreads();
        #pragma unroll
        for (int j = 0; j < 8; j++) {
            int u = tid + j * 256;
            int r = u >> 3, c8 = (u & 7) * 8;
            const float* wsrc = Wo + (size_t)r * 256 + ck * 64 + c8;
            float4 wa = *reinterpret_cast<const float4*>(wsrc);
            float4 wb = *reinterpret_cast<const float4*>(wsrc + 4);
            *reinterpret_cast<uint4*>(sW + r * OSTR + c8) =
                make_uint4(packbf2(wa.x, wa.y), packbf2(wa.z, wa.w),
                           packbf2(wb.x, wb.y), packbf2(wb.z, wb.w));
        }
        #pragma unroll
        for (int j = 0; j < 2; j++) {
            int u = tid + j * 256;
            int r = u >> 3, c8 = (u & 7) * 8;
            *reinterpret_cast<uint4*>(sH + r * OSTR + c8) =
                *reinterpret_cast<const uint4*>(Hb + (size_t)r * DV + ck * 64 + c8);
        }
        __syncthreads();

        #pragma unroll
        for (int kk = 0; kk < 4; kk++) {
            uint32_t bf[4][4];
            #pragma unroll
            for (int p = 0; p < 4; p++)
                ldm_x4(bf[p][0], bf[p][1], bf[p][2], bf[p][3], bBase + (p * 16 * OSTR + kk * 16) * 2);
            #pragma unroll
            for (int mt = 0; mt < 2; mt++) {
                uint32_t a0, a1, a2, a3;
                ldm_x4(a0, a1, a2, a3, aBase + (mt * 16 * OSTR + kk * 16) * 2);
                #pragma unroll
                for (int p = 0; p < 4; p++) {
                    mma_bf16(acc[mt][2*p][0],   acc[mt][2*p][1],   acc[mt][2*p][2],   acc[mt][2*p][3],   a0, a1, a2, a3, bf[p][0], bf[p][1]);
                    mma_bf16(acc[mt][2*p+1][0], acc[mt][2*p+1][1], acc[mt][2*p+1][2], acc[mt][2*p+1][3], a0, a1, a2, a3, bf[p][2], bf[p][3]);
                }
            }
        }
    }

    #pragma unroll
    for (int mt = 0; mt < 2; mt++) {
        int f = warp * 32 + mt * 16 + (lane >> 2);
        float bias0 = bo[f], bias1 = bo[f + 8];
        #pragma unroll
        for (int nt = 0; nt < 8; nt++) {
            int n = n0 + nt * 8 + (lane & 3) * 2;
            size_t i0 = ((size_t)(b * 256 + f)) * HW + n;
            float2 xv0 = *reinterpret_cast<const float2*>(x + i0);
            float2 ov0 = make_float2(xv0.x + acc[mt][nt][0] + bias0, xv0.y + acc[mt][nt][1] + bias0);
            *reinterpret_cast<float2*>(out + i0) = ov0;
            size_t i1 = i0 + (size_t)8 * HW;
            float2 xv1 = *reinterpret_cast<const float2*>(x + i1);
            float2 ov1 = make_float2(xv1.x + acc[mt][nt][2] + bias1, xv1.y + acc[mt][nt][3] + bias1);
            *reinterpret_cast<float2*>(out + i1) = ov1;
        }
    }
}

// ---------------- launch ----------------
extern "C" void kernel_launch(void* const* d_in, const int* in_sizes, int n_in,
                              void* d_out, int out_size) {
    const float* x  = (const float*)d_in[0];
    const float* y  = (const float*)d_in[1];
    const float* Wq = (const float*)d_in[2];
    const float* bq = (const float*)d_in[3];
    const float* Wk = (const float*)d_in[4];
    const float* bk = (const float*)d_in[5];
    const float* Wv = (const float*)d_in[6];
    const float* bv = (const float*)d_in[7];
    const float* Wo = (const float*)d_in[8];
    const float* bo = (const float*)d_in[9];
    float* out = (float*)d_out;

    cudaFuncSetAttribute(proj_mma_kernel, cudaFuncAttributeMaxDynamicSharedMemorySize, PROJ_SMEM);
    proj_mma_kernel<<<dim3(HW / 64, BATCH), 256, PROJ_SMEM>>>(x, y, Wq, Wk, Wv, bq, bk, bv);

    cudaFuncSetAttribute(flash_kernel, cudaFuncAttributeMaxDynamicSharedMemorySize, FLASH_SMEM);
    flash_kernel<<<dim3(HW / 128, BATCH), 256, FLASH_SMEM>>>();

    cudaFuncSetAttribute(out_mma_kernel, cudaFuncAttributeMaxDynamicSharedMemorySize, OUT_SMEM);
    out_mma_kernel<<<dim3(HW / 64, BATCH), 256, OUT_SMEM>>>(x, Wo, bo, out);
}

// round 17
// speedup vs baseline: 1.6389x; 1.6389x over previous
#include <cuda_runtime.h>
#include <cuda_bf16.h>
#include <cstdint>

#define BATCH 8
#define HW    4096
#define CIN   256
#define DQK   128
#define DV    256
#define QS2C  0.12751741f   // (1/sqrt(128)) * log2(e)

__device__ __nv_bfloat16 g_Wqkv[512 * 256];
__device__ __nv_bfloat16 g_Wob[256 * 256];
__device__ __nv_bfloat16 g_Q[(size_t)BATCH * HW * DQK];    // [b][n][d]
__device__ __nv_bfloat16 g_K[(size_t)BATCH * HW * DQK];    // [b][n][d]
__device__ __nv_bfloat16 g_V[(size_t)BATCH * DV * HW];     // [b][e][n] e-major
__device__ __nv_bfloat16 g_Hb[(size_t)BATCH * HW * DV];    // [b][n][e], normalized
__device__ float         g_Qn[(size_t)BATCH * HW];         // QS2C*1.01*||q||
__device__ float         g_Kn[(size_t)BATCH * HW];         // ||k||

__device__ __forceinline__ uint32_t smem_u32(const void* p) {
    return (uint32_t)__cvta_generic_to_shared(p);
}
__device__ __forceinline__ void ldm_x4(uint32_t& r0, uint32_t& r1, uint32_t& r2, uint32_t& r3, uint32_t addr) {
    asm volatile("ldmatrix.sync.aligned.m8n8.x4.shared.b16 {%0,%1,%2,%3},[%4];"
                 : "=r"(r0), "=r"(r1), "=r"(r2), "=r"(r3) : "r"(addr));
}
__device__ __forceinline__ void ldm_x4t(uint32_t& r0, uint32_t& r1, uint32_t& r2, uint32_t& r3, uint32_t addr) {
    asm volatile("ldmatrix.sync.aligned.m8n8.x4.trans.shared.b16 {%0,%1,%2,%3},[%4];"
                 : "=r"(r0), "=r"(r1), "=r"(r2), "=r"(r3) : "r"(addr));
}
__device__ __forceinline__ void mma_bf16(float& c0, float& c1, float& c2, float& c3,
                                         uint32_t a0, uint32_t a1, uint32_t a2, uint32_t a3,
                                         uint32_t b0, uint32_t b1) {
    asm volatile("mma.sync.aligned.m16n8k16.row.col.f32.bf16.bf16.f32 "
                 "{%0,%1,%2,%3},{%4,%5,%6,%7},{%8,%9},{%0,%1,%2,%3};"
                 : "+f"(c0), "+f"(c1), "+f"(c2), "+f"(c3)
                 : "r"(a0), "r"(a1), "r"(a2), "r"(a3), "r"(b0), "r"(b1));
}
__device__ __forceinline__ uint32_t packbf2(float lo, float hi) {
    __nv_bfloat162 v = __floats2bfloat162_rn(lo, hi);
    return *reinterpret_cast<uint32_t*>(&v);
}
__device__ __forceinline__ float ex2f(float x) {
    float y; asm("ex2.approx.f32 %0,%1;" : "=f"(y) : "f"(x)); return y;
}
#define CP16(saddr, gptr) \
    asm volatile("cp.async.cg.shared.global [%0],[%1],16;" :: "r"(saddr), "l"(gptr))
#define CP_COMMIT() asm volatile("cp.async.commit_group;")
#define CP_WAIT1()  asm volatile("cp.async.wait_group 1;")
#define CP_WAIT0()  asm volatile("cp.async.wait_group 0;")

// ---------------- merged weight conversion (single launch) ----------------
__global__ __launch_bounds__(256) void cvtW_kernel(const float* __restrict__ Wq, const float* __restrict__ Wk,
                                                   const float* __restrict__ Wv, const float* __restrict__ Wo) {
    int bid = blockIdx.x;
    const float* src; __nv_bfloat16* dst; int off;
    if (bid < 32)       { src = Wq; dst = g_Wqkv;         off = bid; }
    else if (bid < 64)  { src = Wk; dst = g_Wqkv + 32768; off = bid - 32; }
    else if (bid < 128) { src = Wv; dst = g_Wqkv + 65536; off = bid - 64; }
    else                { src = Wo; dst = g_Wob;          off = bid - 128; }
    int i = (off * 256 + threadIdx.x) * 4;
    float4 v = *reinterpret_cast<const float4*>(src + i);
    uint2 o;
    o.x = packbf2(v.x, v.y);
    o.y = packbf2(v.z, v.w);
    *reinterpret_cast<uint2*>(dst + i) = o;
}

// ---------------- projection GEMM (bf16 mma), fused input-cvt + norms ----------------
#define PSTR 72
#define PROJ_SMEM ((128 * PSTR + 512 * PSTR) * 2)

__global__ __launch_bounds__(256, 1) void proj_mma_kernel(
        const float* __restrict__ x, const float* __restrict__ y,
        const float* __restrict__ bq, const float* __restrict__ bk, const float* __restrict__ bv) {
    extern __shared__ __nv_bfloat16 psmem[];
    __nv_bfloat16* sX = psmem;
    __nv_bfloat16* sY = psmem + 64 * PSTR;
    __nv_bfloat16* sW = psmem + 128 * PSTR;
    __shared__ float sBias[512];

    const int b = blockIdx.y, n0 = blockIdx.x * 64;
    const int tid = threadIdx.x, warp = tid >> 5, lane = tid & 31;
    const int mg = warp & 3, dg = warp >> 2;

    for (int i = tid; i < 512; i += 256)
        sBias[i] = (i < 128) ? bq[i] : (i < 256) ? bk[i - 128] : bv[i - 256];

    const float* Xf = x + (size_t)b * CIN * HW + n0;
    const float* Yf = y + (size_t)b * CIN * HW + n0;

    float acc[32][4];
    #pragma unroll
    for (int t = 0; t < 32; t++) { acc[t][0] = acc[t][1] = acc[t][2] = acc[t][3] = 0.f; }

    const int arow = (lane & 7) + ((lane >> 4) & 1) * 8;
    const int acol = mg * 16 + ((lane >> 3) & 1) * 8;
    const uint32_t aXbase = smem_u32(sX + arow * PSTR + acol);
    const uint32_t aYbase = smem_u32(sY + arow * PSTR + acol);
    const int brow = (lane & 7) + ((lane >> 4) & 1) * 8;
    const int bcol = ((lane >> 3) & 1) * 8;
    const uint32_t bWbase = smem_u32(sW + (dg * 256 + brow) * PSTR + bcol);

    for (int ck = 0; ck < 4; ck++) {
        __syncthreads();
        #pragma unroll
        for (int j = 0; j < 4; j++) {
            int u = tid + j * 256;
            int r = u >> 3, c8 = (u & 7) * 8;
            const float* xs = Xf + (size_t)(ck * 64 + r) * HW + c8;
            const float* ys = Yf + (size_t)(ck * 64 + r) * HW + c8;
            float4 xa = *reinterpret_cast<const float4*>(xs);
            float4 xb2 = *reinterpret_cast<const float4*>(xs + 4);
            float4 ya = *reinterpret_cast<const float4*>(ys);
            float4 yb2 = *reinterpret_cast<const float4*>(ys + 4);
            *reinterpret_cast<uint4*>(sX + r * PSTR + c8) =
                make_uint4(packbf2(xa.x, xa.y), packbf2(xa.z, xa.w),
                           packbf2(xb2.x, xb2.y), packbf2(xb2.z, xb2.w));
            *reinterpret_cast<uint4*>(sY + r * PSTR + c8) =
                make_uint4(packbf2(ya.x, ya.y), packbf2(ya.z, ya.w),
                           packbf2(yb2.x, yb2.y), packbf2(yb2.z, yb2.w));
        }
        #pragma unroll
        for (int j = 0; j < 16; j++) {
            int u = tid + j * 256;
            int r = u >> 3, c8 = (u & 7) * 8;
            *reinterpret_cast<uint4*>(sW + r * PSTR + c8) =
                *reinterpret_cast<const uint4*>(g_Wqkv + (size_t)r * 256 + ck * 64 + c8);
        }
        __syncthreads();

        #pragma unroll
        for (int kk = 0; kk < 4; kk++) {
            uint32_t ax0, ax1, ax2, ax3;
            ldm_x4t(ax0, ax1, ax2, ax3, aXbase + kk * 16 * PSTR * 2);
            uint32_t ay0 = ax0, ay1 = ax1, ay2 = ax2, ay3 = ax3;
            if (dg == 0) ldm_x4t(ay0, ay1, ay2, ay3, aYbase + kk * 16 * PSTR * 2);
            #pragma unroll
            for (int t2 = 0; t2 < 16; t2++) {
                uint32_t b0, b1, b2, b3;
                ldm_x4(b0, b1, b2, b3, bWbase + (t2 * 16 * PSTR + kk * 16) * 2);
                if (dg == 0 && t2 < 8) {
                    mma_bf16(acc[2*t2][0],   acc[2*t2][1],   acc[2*t2][2],   acc[2*t2][3],   ay0, ay1, ay2, ay3, b0, b1);
                    mma_bf16(acc[2*t2+1][0], acc[2*t2+1][1], acc[2*t2+1][2], acc[2*t2+1][3], ay0, ay1, ay2, ay3, b2, b3);
                } else {
                    mma_bf16(acc[2*t2][0],   acc[2*t2][1],   acc[2*t2][2],   acc[2*t2][3],   ax0, ax1, ax2, ax3, b0, b1);
                    mma_bf16(acc[2*t2+1][0], acc[2*t2+1][1], acc[2*t2+1][2], acc[2*t2+1][3], ax0, ax1, ax2, ax3, b2, b3);
                }
            }
        }
    }

    const int r = n0 + mg * 16 + (lane >> 2);
    const int cpair = (lane & 3) * 2;
    float qn0 = 0.f, qn1 = 0.f, kn0 = 0.f, kn1 = 0.f;
    #pragma unroll
    for (int t = 0; t < 32; t++) {
        int d0 = dg * 256 + t * 8 + cpair;
        float bv0 = sBias[d0], bv1 = sBias[d0 + 1];
        float v00 = acc[t][0] + bv0, v01 = acc[t][1] + bv1;
        float v10 = acc[t][2] + bv0, v11 = acc[t][3] + bv1;
        if (d0 < 256) {
            __nv_bfloat16* dst = (d0 < 128) ? g_Q : g_K;
            int ld = d0 & 127;
            *reinterpret_cast<uint32_t*>(dst + ((size_t)b * HW + r) * DQK + ld) = packbf2(v00, v01);
            *reinterpret_cast<uint32_t*>(dst + ((size_t)b * HW + r + 8) * DQK + ld) = packbf2(v10, v11);
            if (d0 < 128) { qn0 += v00 * v00 + v01 * v01; qn1 += v10 * v10 + v11 * v11; }
            else          { kn0 += v00 * v00 + v01 * v01; kn1 += v10 * v10 + v11 * v11; }
        } else {
            int e = d0 - 256;
            __nv_bfloat16* base = g_V + (size_t)b * DV * HW;
            base[(size_t)e * HW + r]           = __float2bfloat16(v00);
            base[(size_t)(e + 1) * HW + r]     = __float2bfloat16(v01);
            base[(size_t)e * HW + r + 8]       = __float2bfloat16(v10);
            base[(size_t)(e + 1) * HW + r + 8] = __float2bfloat16(v11);
        }
    }
    if (dg == 0) {
        qn0 += __shfl_xor_sync(0xffffffffu, qn0, 1); qn0 += __shfl_xor_sync(0xffffffffu, qn0, 2);
        qn1 += __shfl_xor_sync(0xffffffffu, qn1, 1); qn1 += __shfl_xor_sync(0xffffffffu, qn1, 2);
        kn0 += __shfl_xor_sync(0xffffffffu, kn0, 1); kn0 += __shfl_xor_sync(0xffffffffu, kn0, 2);
        kn1 += __shfl_xor_sync(0xffffffffu, kn1, 1); kn1 += __shfl_xor_sync(0xffffffffu, kn1, 2);
        if ((lane & 3) == 0) {
            const float qsc = QS2C * 1.01f;
            g_Qn[(size_t)b * HW + r]     = sqrtf(qn0) * qsc;
            g_Qn[(size_t)b * HW + r + 8] = sqrtf(qn1) * qsc;
            g_Kn[(size_t)b * HW + r]     = sqrtf(kn0);
            g_Kn[(size_t)b * HW + r + 8] = sqrtf(kn1);
        }
    }
}

// ---------------- flash: bf16, bound softmax, Q in regs, triple-buffered KV,
//                  software-pipelined ldmatrix ----------------
#define QSTRB 272
#define VSTRB 144
#define KBUF (64 * QSTRB)
#define VBUF (256 * VSTRB)
#define SK_OFF (128 * QSTRB)
#define SV_OFF (SK_OFF + 3 * KBUF)
#define FLASH_SMEM (SV_OFF + 3 * VBUF)   // 197632

__global__ __launch_bounds__(256, 1) void flash_kernel() {
    extern __shared__ uint8_t fsm[];
    uint8_t* sQ = fsm;
    uint8_t* sK = fsm + SK_OFF;
    uint8_t* sV = fsm + SV_OFF;
    __shared__ float s_km[8];

    const int b = blockIdx.y, q0 = blockIdx.x * 128;
    const int tid = threadIdx.x, warp = tid >> 5, lane = tid & 31;
    const uint8_t* Qg = reinterpret_cast<const uint8_t*>(g_Q + ((size_t)b * HW + q0) * DQK);
    const uint8_t* Kg = reinterpret_cast<const uint8_t*>(g_K + (size_t)b * HW * DQK);
    const uint8_t* Vg = reinterpret_cast<const uint8_t*>(g_V + (size_t)b * DV * HW);

    #pragma unroll
    for (int j = 0; j < 8; j++) {
        int u = tid + j * 256; int r = u >> 4, s = (u & 15) * 16;
        CP16(smem_u32(sQ + r * QSTRB + s), Qg + (size_t)r * 256 + s);
    }
    #pragma unroll
    for (int j = 0; j < 4; j++) {
        int u = tid + j * 256; int r = u >> 4, s = (u & 15) * 16;
        CP16(smem_u32(sK + r * QSTRB + s), Kg + (size_t)r * 256 + s);
    }
    #pragma unroll
    for (int j = 0; j < 8; j++) {
        int u = tid + j * 256; int e = u >> 3, s = (u & 7) * 16;
        CP16(smem_u32(sV + e * VSTRB + s), Vg + (size_t)e * (HW * 2) + s);
    }
    CP_COMMIT();
    #pragma unroll
    for (int j = 0; j < 4; j++) {
        int u = tid + j * 256; int r = u >> 4, s = (u & 15) * 16;
        CP16(smem_u32(sK + KBUF + r * QSTRB + s), Kg + (size_t)(64 + r) * 256 + s);
    }
    #pragma unroll
    for (int j = 0; j < 8; j++) {
        int u = tid + j * 256; int e = u >> 3, s = (u & 7) * 16;
        CP16(smem_u32(sV + VBUF + e * VSTRB + s), Vg + (size_t)e * (HW * 2) + 128 + s);
    }
    CP_COMMIT();

    {
        float km = 0.f;
        const float* Kn = g_Kn + (size_t)b * HW;
        #pragma unroll
        for (int i = 0; i < HW / 256; i++) km = fmaxf(km, Kn[tid + i * 256]);
        #pragma unroll
        for (int o = 16; o > 0; o >>= 1) km = fmaxf(km, __shfl_xor_sync(0xffffffffu, km, o));
        if (lane == 0) s_km[warp] = km;
    }

    float O[32][4];
    #pragma unroll
    for (int n = 0; n < 32; n++) { O[n][0] = O[n][1] = O[n][2] = O[n][3] = 0.f; }
    float l0 = 0.f, l1 = 0.f;
    float m0 = 0.f, m1 = 0.f;

    const int prow = lane >> 2;
    const uint32_t aQ = smem_u32(sQ + (warp * 16 + (lane & 15)) * QSTRB + ((lane >> 4) & 1) * 16);
    const int bRow = (lane & 7) + ((lane >> 4) & 1) * 8;
    const int bCol = ((lane >> 3) & 1) * 16;
    uint32_t qf[8][4];
    uint32_t rb[3][4];

    for (int t = 0; t < 64; t++) {
        if (t < 63) { CP_WAIT1(); } else { CP_WAIT0(); }
        __syncthreads();

        if (t + 2 < 64) {
            int kv2 = (t + 2) * 64;
            uint8_t* dK = sK + ((t + 2) % 3) * KBUF;
            uint8_t* dV = sV + ((t + 2) % 3) * VBUF;
            #pragma unroll
            for (int j = 0; j < 4; j++) {
                int u = tid + j * 256; int r = u >> 4, s = (u & 15) * 16;
                CP16(smem_u32(dK + r * QSTRB + s), Kg + (size_t)(kv2 + r) * 256 + s);
            }
            #pragma unroll
            for (int j = 0; j < 8; j++) {
                int u = tid + j * 256; int e = u >> 3, s = (u & 7) * 16;
                CP16(smem_u32(dV + e * VSTRB + s), Vg + (size_t)e * (HW * 2) + kv2 * 2 + s);
            }
            CP_COMMIT();
        }

        if (t == 0) {
            float kmax = s_km[0];
            #pragma unroll
            for (int w = 1; w < 8; w++) kmax = fmaxf(kmax, s_km[w]);
            m0 = g_Qn[(size_t)b * HW + q0 + warp * 16 + prow] * kmax;
            m1 = g_Qn[(size_t)b * HW + q0 + warp * 16 + prow + 8] * kmax;
            #pragma unroll
            for (int kk = 0; kk < 8; kk++)
                ldm_x4(qf[kk][0], qf[kk][1], qf[kk][2], qf[kk][3], aQ + kk * 32);
        }

        const int bi = t % 3;
        const uint32_t bK = smem_u32(sK + bi * KBUF + bRow * QSTRB + bCol);
        const uint32_t bV = smem_u32(sV + bi * VBUF + bRow * VSTRB + bCol);

        float S[8][4];
        #pragma unroll
        for (int j = 0; j < 8; j++) { S[j][0] = S[j][1] = S[j][2] = S[j][3] = 0.f; }
        ldm_x4(rb[0][0], rb[0][1], rb[0][2], rb[0][3], bK);
        ldm_x4(rb[1][0], rb[1][1], rb[1][2], rb[1][3], bK + 16 * QSTRB);
        #pragma unroll
        for (int s5 = 0; s5 < 32; s5++) {
            if (s5 + 2 < 32) {
                int s2 = s5 + 2, kk2 = s2 >> 2, j22 = s2 & 3;
                ldm_x4(rb[s2 % 3][0], rb[s2 % 3][1], rb[s2 % 3][2], rb[s2 % 3][3],
                       bK + j22 * 16 * QSTRB + kk2 * 32);
            }
            int kk = s5 >> 2, j2 = s5 & 3;
            uint32_t* bb = rb[s5 % 3];
            mma_bf16(S[2*j2][0],   S[2*j2][1],   S[2*j2][2],   S[2*j2][3],
                     qf[kk][0], qf[kk][1], qf[kk][2], qf[kk][3], bb[0], bb[1]);
            mma_bf16(S[2*j2+1][0], S[2*j2+1][1], S[2*j2+1][2], S[2*j2+1][3],
                     qf[kk][0], qf[kk][1], qf[kk][2], qf[kk][3], bb[2], bb[3]);
        }

        float rs0 = 0.f, rs1 = 0.f;
        #pragma unroll
        for (int j = 0; j < 8; j++) {
            S[j][0] = ex2f(fmaf(S[j][0], QS2C, -m0));
            S[j][1] = ex2f(fmaf(S[j][1], QS2C, -m0));
            S[j][2] = ex2f(fmaf(S[j][2], QS2C, -m1));
            S[j][3] = ex2f(fmaf(S[j][3], QS2C, -m1));
            rs0 += S[j][0] + S[j][1];
            rs1 += S[j][2] + S[j][3];
        }
        l0 += rs0;
        l1 += rs1;

        uint32_t a0 = 0, a1 = 0, a2 = 0, a3 = 0;
        ldm_x4(rb[0][0], rb[0][1], rb[0][2], rb[0][3], bV);
        ldm_x4(rb[1][0], rb[1][1], rb[1][2], rb[1][3], bV + 16 * VSTRB);
        #pragma unroll
        for (int s5 = 0; s5 < 64; s5++) {
            if (s5 + 2 < 64) {
                int s2 = s5 + 2, kc2 = s2 >> 4, ep2 = s2 & 15;
                ldm_x4(rb[s2 % 3][0], rb[s2 % 3][1], rb[s2 % 3][2], rb[s2 % 3][3],
                       bV + ep2 * 16 * VSTRB + kc2 * 32);
            }
            int kc = s5 >> 4, ep = s5 & 15;
            if (ep == 0) {
                a0 = packbf2(S[2*kc][0],   S[2*kc][1]);
                a1 = packbf2(S[2*kc][2],   S[2*kc][3]);
                a2 = packbf2(S[2*kc+1][0], S[2*kc+1][1]);
                a3 = packbf2(S[2*kc+1][2], S[2*kc+1][3]);
            }
            uint32_t* bb = rb[s5 % 3];
            mma_bf16(O[2*ep][0],   O[2*ep][1],   O[2*ep][2],   O[2*ep][3],   a0, a1, a2, a3, bb[0], bb[1]);
            mma_bf16(O[2*ep+1][0], O[2*ep+1][1], O[2*ep+1][2], O[2*ep+1][3], a0, a1, a2, a3, bb[2], bb[3]);
        }
    }

    l0 += __shfl_xor_sync(0xffffffffu, l0, 1);
    l0 += __shfl_xor_sync(0xffffffffu, l0, 2);
    l1 += __shfl_xor_sync(0xffffffffu, l1, 1);
    l1 += __shfl_xor_sync(0xffffffffu, l1, 2);
    const float inv0 = 1.f / l0, inv1 = 1.f / l1;
    const int r0 = q0 + warp * 16 + prow;
    uint32_t* H0 = reinterpret_cast<uint32_t*>(g_Hb + ((size_t)b * HW + r0) * DV) + (lane & 3);
    uint32_t* H1 = H0 + 8 * (DV / 2);
    #pragma unroll
    for (int n = 0; n < 32; n++) {
        H0[n * 4] = packbf2(O[n][0] * inv0, O[n][1] * inv0);
        H1[n * 4] = packbf2(O[n][2] * inv1, O[n][3] * inv1);
    }
}

// ---------------- output GEMM + residual (bf16 mma) ----------------
#define OSTR 72
#define OUT_SMEM ((256 * OSTR + 64 * OSTR) * 2)

__global__ __launch_bounds__(256) void out_mma_kernel(
        const float* __restrict__ x, const float* __restrict__ bo, float* __restrict__ out) {
    extern __shared__ __nv_bfloat16 osmem[];
    __nv_bfloat16* sW = osmem;
    __nv_bfloat16* sH = osmem + 256 * OSTR;
    const int b = blockIdx.y, n0 = blockIdx.x * 64;
    const int tid = threadIdx.x, warp = tid >> 5, lane = tid & 31;

    const __nv_bfloat16* Hb = g_Hb + ((size_t)b * HW + n0) * DV;

    float acc[2][8][4];
    #pragma unroll
    for (int mt = 0; mt < 2; mt++)
        #pragma unroll
        for (int nt = 0; nt < 8; nt++) { acc[mt][nt][0] = acc[mt][nt][1] = acc[mt][nt][2] = acc[mt][nt][3] = 0.f; }

    const int arow = lane & 15;
    const int acol = ((lane >> 4) & 1) * 8;
    const uint32_t aBase = smem_u32(sW + (warp * 32 + arow) * OSTR + acol);
    const int brow = (lane & 7) + ((lane >> 4) & 1) * 8;
    const int bcol = ((lane >> 3) & 1) * 8;
    const uint32_t bBase = smem_u32(sH + brow * OSTR + bcol);

    for (int ck = 0; ck < 4; ck++) {
        __syncthreads();
        #pragma unroll
        for (int j = 0; j < 8; j++) {
            int u = tid + j * 256;
            int r = u >> 3, c8 = (u & 7) * 8;
            *reinterpret_cast<uint4*>(sW + r * OSTR + c8) =
                *reinterpret_cast<const uint4*>(g_Wob + (size_t)r * 256 + ck * 64 + c8);
        }
        #pragma unroll
        for (int j = 0; j < 2; j++) {
            int u = tid + j * 256;
            int r = u >> 3, c8 = (u & 7) * 8;
            *reinterpret_cast<uint4*>(sH + r * OSTR + c8) =
                *reinterpret_cast<const uint4*>(Hb + (size_t)r * DV + ck * 64 + c8);
        }
        __syncthreads();

        #pragma unroll
        for (int kk = 0; kk < 4; kk++) {
            uint32_t bf[4][4];
            #pragma unroll
            for (int p = 0; p < 4; p++)
                ldm_x4(bf[p][0], bf[p][1], bf[p][2], bf[p][3], bBase + (p * 16 * OSTR + kk * 16) * 2);
            #pragma unroll
            for (int mt = 0; mt < 2; mt++) {
                uint32_t a0, a1, a2, a3;
                ldm_x4(a0, a1, a2, a3, aBase + (mt * 16 * OSTR + kk * 16) * 2);
                #pragma unroll
                for (int p = 0; p < 4; p++) {
                    mma_bf16(acc[mt][2*p][0],   acc[mt][2*p][1],   acc[mt][2*p][2],   acc[mt][2*p][3],   a0, a1, a2, a3, bf[p][0], bf[p][1]);
                    mma_bf16(acc[mt][2*p+1][0], acc[mt][2*p+1][1], acc[mt][2*p+1][2], acc[mt][2*p+1][3], a0, a1, a2, a3, bf[p][2], bf[p][3]);
                }
            }
        }
    }

    #pragma unroll
    for (int mt = 0; mt < 2; mt++) {
        int f = warp * 32 + mt * 16 + (lane >> 2);
        float bias0 = bo[f], bias1 = bo[f + 8];
        #pragma unroll
        for (int nt = 0; nt < 8; nt++) {
            int n = n0 + nt * 8 + (lane & 3) * 2;
            size_t i0 = ((size_t)(b * 256 + f)) * HW + n;
            float2 xv0 = *reinterpret_cast<const float2*>(x + i0);
            float2 ov0 = make_float2(xv0.x + acc[mt][nt][0] + bias0, xv0.y + acc[mt][nt][1] + bias0);
            *reinterpret_cast<float2*>(out + i0) = ov0;
            size_t i1 = i0 + (size_t)8 * HW;
            float2 xv1 = *reinterpret_cast<const float2*>(x + i1);
            float2 ov1 = make_float2(xv1.x + acc[mt][nt][2] + bias1, xv1.y + acc[mt][nt][3] + bias1);
            *reinterpret_cast<float2*>(out + i1) = ov1;
        }
    }
}

// ---------------- launch ----------------
extern "C" void kernel_launch(void* const* d_in, const int* in_sizes, int n_in,
                              void* d_out, int out_size) {
    const float* x  = (const float*)d_in[0];
    const float* y  = (const float*)d_in[1];
    const float* Wq = (const float*)d_in[2];
    const float* bq = (const float*)d_in[3];
    const float* Wk = (const float*)d_in[4];
    const float* bk = (const float*)d_in[5];
    const float* Wv = (const float*)d_in[6];
    const float* bv = (const float*)d_in[7];
    const float* Wo = (const float*)d_in[8];
    const float* bo = (const float*)d_in[9];
    float* out = (float*)d_out;

    cvtW_kernel<<<192, 256>>>(Wq, Wk, Wv, Wo);

    cudaFuncSetAttribute(proj_mma_kernel, cudaFuncAttributeMaxDynamicSharedMemorySize, PROJ_SMEM);
    proj_mma_kernel<<<dim3(HW / 64, BATCH), 256, PROJ_SMEM>>>(x, y, bq, bk, bv);

    cudaFuncSetAttribute(flash_kernel, cudaFuncAttributeMaxDynamicSharedMemorySize, FLASH_SMEM);
    flash_kernel<<<dim3(HW / 128, BATCH), 256, FLASH_SMEM>>>();

    cudaFuncSetAttribute(out_mma_kernel, cudaFuncAttributeMaxDynamicSharedMemorySize, OUT_SMEM);
    out_mma_kernel<<<dim3(HW / 64, BATCH), 256, OUT_SMEM>>>(x, bo, out);
}